// round 4
// baseline (speedup 1.0000x reference)
#include <cuda_runtime.h>
#include <mma.h>

using namespace nvcuda;

#define NN    100000
#define EE    1600000
#define HID   64
#define HID2  128
#define EDIM  16
#define INDIM 32

// ---------------- scratch (device globals; no allocation) ----------------
__device__ float  g_hA[NN * HID];
__device__ float  g_hB[NN * HID];
__device__ float  g_tmp[NN * HID];
__device__ int    g_deg[NN];
__device__ int    g_cnt[NN];
__device__ int    g_rowptr[NN + 1];
__device__ int    g_blksum[256];
__device__ int    g_srcp[EE];            // src index permuted to CSR order
__device__ float4 g_eap2[EE * 8];        // edge_attr CSR-ordered, duplicated (a,a) pairs

// ---------------- f32x2 packed helpers ----------------
union PF { float2 f2; unsigned long long u; };

__device__ __forceinline__ unsigned long long fma2(unsigned long long a,
                                                   unsigned long long b,
                                                   unsigned long long c) {
    unsigned long long d;
    asm("fma.rn.f32x2 %0, %1, %2, %3;" : "=l"(d) : "l"(a), "l"(b), "l"(c));
    return d;
}
__device__ __forceinline__ unsigned long long add2(unsigned long long a,
                                                   unsigned long long b) {
    unsigned long long d;
    asm("add.rn.f32x2 %0, %1, %2;" : "=l"(d) : "l"(a), "l"(b));
    return d;
}

// tf32 round-to-nearest (13-bit truncation)
__device__ __forceinline__ float tf32r(float x) {
    unsigned int u = __float_as_uint(x);
    u = (u + 0x1000u) & 0xFFFFE000u;
    return __uint_as_float(u);
}

// ---------------- CSR build ----------------
__global__ void k_zero(int N) {
    int i = blockIdx.x * blockDim.x + threadIdx.x;
    if (i < N) { g_deg[i] = 0; g_cnt[i] = 0; }
}

__global__ void k_hist(const int* __restrict__ dst, int E) {
    int e = blockIdx.x * blockDim.x + threadIdx.x;
    if (e < E) atomicAdd(&g_deg[dst[e]], 1);
}

__global__ void k_scan1(int N) {
    __shared__ int sh[1024];
    int i = blockIdx.x * 1024 + threadIdx.x;
    int v = (i < N) ? g_deg[i] : 0;
    sh[threadIdx.x] = v;
    __syncthreads();
    for (int off = 1; off < 1024; off <<= 1) {
        int add = (threadIdx.x >= off) ? sh[threadIdx.x - off] : 0;
        __syncthreads();
        sh[threadIdx.x] += add;
        __syncthreads();
    }
    if (i < N) g_rowptr[i] = sh[threadIdx.x] - v;     // exclusive
    if (threadIdx.x == 1023) g_blksum[blockIdx.x] = sh[1023];
}

__global__ void k_scan2(int B) {
    if (blockIdx.x == 0 && threadIdx.x == 0) {
        int acc = 0;
        for (int b = 0; b < B; b++) { int t = g_blksum[b]; g_blksum[b] = acc; acc += t; }
    }
}

__global__ void k_scan3(int N, int E) {
    int i = blockIdx.x * 1024 + threadIdx.x;
    if (i < N) g_rowptr[i] += g_blksum[blockIdx.x];
    if (i == 0) g_rowptr[N] = E;
}

// scatter: CSR-permute src; write edge_attr duplicated as (a,a) f32x2 pairs
__global__ void k_scatter(const int* __restrict__ src, const int* __restrict__ dst,
                          const float4* __restrict__ ea, int E) {
    int e = blockIdx.x * blockDim.x + threadIdx.x;
    if (e >= E) return;
    int d = dst[e];
    int p = g_rowptr[d] + atomicAdd(&g_cnt[d], 1);
    g_srcp[p] = src[e];
#pragma unroll
    for (int j = 0; j < 4; j++) {
        float4 a = __ldg(ea + e * 4 + j);
        g_eap2[p * 8 + 2 * j + 0] = make_float4(a.x, a.x, a.y, a.y);
        g_eap2[p * 8 + 2 * j + 1] = make_float4(a.z, a.z, a.w, a.w);
    }
}

// ---------------- input linear: h = x @ src_w + src_b ----------------
__global__ void k_inlin(const float* __restrict__ x, const float* __restrict__ w,
                        const float* __restrict__ b, int N) {
    int idx = blockIdx.x * blockDim.x + threadIdx.x;
    if (idx >= N * HID) return;
    int n = idx >> 6, c = idx & 63;
    const float* xr = x + n * INDIM;
    float acc = __ldg(&b[c]);
#pragma unroll
    for (int k = 0; k < INDIM; k++)
        acc = fmaf(__ldg(&xr[k]), __ldg(&w[k * HID + c]), acc);
    g_hA[idx] = acc;
}

// ---------------- aggregation: warp-per-node online softmax, f32x2 edge GEMV
// dir=0: read g_hA; dir=1: read g_hB. Writes g_tmp.
__global__ void __launch_bounds__(256)
k_agg(int dir, const float* __restrict__ ew, const float* __restrict__ ebias, int N) {
    const float* hin = dir ? g_hB : g_hA;
    int warp = threadIdx.x >> 5, lane = threadIdx.x & 31;
    int n = blockIdx.x * 8 + warp;
    if (n >= N) return;

    // preload ew columns for this lane's two channels: (ew[k][2l], ew[k][2l+1])
    PF ew2[EDIM];
#pragma unroll
    for (int k = 0; k < EDIM; k++)
        ew2[k].f2 = __ldg((const float2*)(ew + k * HID) + lane);
    PF eb; eb.f2 = __ldg((const float2*)ebias + lane);

    int beg = g_rowptr[n], end = g_rowptr[n + 1];
    float m0 = -1e30f, m1 = -1e30f;
    float s0 = 0.f, s1 = 0.f, t0 = 0.f, t1 = 0.f;

#pragma unroll 2
    for (int i = beg; i < end; i++) {
        int sv = __ldg(&g_srcp[i]);
        float2 h = __ldg((const float2*)(hin + sv * HID) + lane);
        const ulonglong2* ep = reinterpret_cast<const ulonglong2*>(g_eap2) + (size_t)i * 8;
        PF va, vb;
        va.u = eb.u;
        vb.f2 = make_float2(0.f, 0.f);
#pragma unroll
        for (int k2 = 0; k2 < 8; k2++) {
            ulonglong2 q = __ldg(ep + k2);
            va.u = fma2(q.x, ew2[2 * k2 + 0].u, va.u);
            vb.u = fma2(q.y, ew2[2 * k2 + 1].u, vb.u);
        }
        PF v; v.u = add2(va.u, vb.u);

        // msg = relu(h+v) + eps; softmax shift-invariant in eps -> add eps at end
        float r0 = fmaxf(h.x + v.f2.x, 0.f);
        float r1 = fmaxf(h.y + v.f2.y, 0.f);

        float nm0 = fmaxf(m0, r0);
        float w0  = __expf(r0 - nm0);
        float c0  = __expf(m0 - nm0);
        s0 = fmaf(s0, c0, w0);
        t0 = fmaf(t0, c0, r0 * w0);
        m0 = nm0;

        float nm1 = fmaxf(m1, r1);
        float w1v = __expf(r1 - nm1);
        float c1  = __expf(m1 - nm1);
        s1 = fmaf(s1, c1, w1v);
        t1 = fmaf(t1, c1, r1 * w1v);
        m1 = nm1;
    }

    float2 hs = __ldg((const float2*)(hin + n * HID) + lane);
    float o0 = (s0 > 0.f ? __fdividef(t0, s0) + 1e-7f : 0.f) + hs.x;
    float o1 = (s1 > 0.f ? __fdividef(t1, s1) + 1e-7f : 0.f) + hs.y;
    *((float2*)(g_tmp + n * HID) + lane) = make_float2(o0, o1);
}

// ---------------- MLP via tf32 tensor cores ----------------
// reads g_tmp; dir=0: write g_hB; dir=1: write g_hA. 64 nodes per block.
// Linear(64->128) -> BN -> ReLU -> Linear(128->64) -> ReLU
__global__ void __launch_bounds__(256)
k_mlp(int dir,
      const float* __restrict__ w1, const float* __restrict__ b1,
      const float* __restrict__ gam, const float* __restrict__ bet,
      const float* __restrict__ w2, const float* __restrict__ b2, int N) {
    float* outp = dir ? g_hA : g_hB;
    extern __shared__ float sm[];
    float* s_x  = sm;                     // [64][64]
    float* s_w1 = sm + 4096;              // [64][128]
    float* s_h  = sm + 4096 + 8192;       // [64][128]
    float* s_w2 = sm + 4096 + 16384;      // [128][64]

    int tid  = threadIdx.x;
    int base = blockIdx.x * 64;

    // stage weights + input tile (tf32-rounded)
    for (int i = tid; i < 8192; i += 256) s_w1[i] = tf32r(__ldg(&w1[i]));
    for (int i = tid; i < 8192; i += 256) s_w2[i] = tf32r(__ldg(&w2[i]));
    {
        const float4* in4 = (const float4*)(g_tmp + base * HID);
        long limit4 = (long)(N - base) * 16;        // float4s per row = 16
        for (int i = tid; i < 1024; i += 256) {
            float4 v = (i < limit4) ? __ldg(in4 + i) : make_float4(0.f, 0.f, 0.f, 0.f);
            v.x = tf32r(v.x); v.y = tf32r(v.y); v.z = tf32r(v.z); v.w = tf32r(v.w);
            ((float4*)s_x)[i] = v;
        }
    }
    __syncthreads();

    int wid = tid >> 5;
    int mt  = wid >> 1;                 // 0..3 : m-tile (16 rows)

    // phase 1: H[64x128] = X[64x64] @ W1[64x128]
    {
        int nb = (wid & 1) * 4;         // 4 n-tiles per warp
        wmma::fragment<wmma::accumulator, 16, 16, 8, float> c[4];
#pragma unroll
        for (int t = 0; t < 4; t++) wmma::fill_fragment(c[t], 0.f);
#pragma unroll
        for (int k = 0; k < 8; k++) {
            wmma::fragment<wmma::matrix_a, 16, 16, 8, wmma::precision::tf32, wmma::row_major> a;
            wmma::load_matrix_sync(a, s_x + mt * 16 * 64 + k * 8, 64);
#pragma unroll
            for (int t = 0; t < 4; t++) {
                wmma::fragment<wmma::matrix_b, 16, 16, 8, wmma::precision::tf32, wmma::row_major> b;
                wmma::load_matrix_sync(b, s_w1 + (k * 8) * 128 + (nb + t) * 16, 128);
                wmma::mma_sync(c[t], a, b, c[t]);
            }
        }
#pragma unroll
        for (int t = 0; t < 4; t++)
            wmma::store_matrix_sync(s_h + mt * 16 * 128 + (nb + t) * 16, c[t], 128,
                                    wmma::mem_row_major);
    }
    __syncthreads();

    // BN + ReLU elementwise (tf32-rounded for phase 2)
    {
        const float BNC = 0.9999950000375f;   // 1/sqrt(1+1e-5)
        for (int i = tid; i < 8192; i += 256) {
            int j = i & 127;
            float v = s_h[i] + __ldg(&b1[j]);
            v = fmaf(v, __ldg(&gam[j]) * BNC, __ldg(&bet[j]));
            s_h[i] = tf32r(fmaxf(v, 0.f));
        }
    }
    __syncthreads();

    // phase 2: O[64x64] = H[64x128] @ W2[128x64]  (into s_x, reused)
    {
        int nb = (wid & 1) * 2;         // 2 n-tiles per warp
        wmma::fragment<wmma::accumulator, 16, 16, 8, float> c[2];
#pragma unroll
        for (int t = 0; t < 2; t++) wmma::fill_fragment(c[t], 0.f);
#pragma unroll
        for (int k = 0; k < 16; k++) {
            wmma::fragment<wmma::matrix_a, 16, 16, 8, wmma::precision::tf32, wmma::row_major> a;
            wmma::load_matrix_sync(a, s_h + mt * 16 * 128 + k * 8, 128);
#pragma unroll
            for (int t = 0; t < 2; t++) {
                wmma::fragment<wmma::matrix_b, 16, 16, 8, wmma::precision::tf32, wmma::row_major> b;
                wmma::load_matrix_sync(b, s_w2 + (k * 8) * 64 + (nb + t) * 16, 64);
                wmma::mma_sync(c[t], a, b, c[t]);
            }
        }
#pragma unroll
        for (int t = 0; t < 2; t++)
            wmma::store_matrix_sync(s_x + mt * 16 * 64 + (nb + t) * 16, c[t], 64,
                                    wmma::mem_row_major);
    }
    __syncthreads();

    // bias + ReLU + writeout
    {
        const float4* b24 = (const float4*)b2;
        for (int i = tid; i < 1024; i += 256) {
            int row = i >> 4, c4 = i & 15;
            int node = base + row;
            if (node < N) {
                float4 v  = ((float4*)s_x)[i];
                float4 bb = __ldg(&b24[c4]);
                v.x = fmaxf(v.x + bb.x, 0.f);
                v.y = fmaxf(v.y + bb.y, 0.f);
                v.z = fmaxf(v.z + bb.z, 0.f);
                v.w = fmaxf(v.w + bb.w, 0.f);
                ((float4*)(outp + node * HID))[c4] = v;
            }
        }
    }
}

// ---------------- head ----------------
__global__ void k_head(const float* __restrict__ gfeat, const int* __restrict__ ngp,
                       const float* __restrict__ hw, const float* __restrict__ hb,
                       float* __restrict__ out, int N, int gfd) {
    int n = blockIdx.x * blockDim.x + threadIdx.x;
    if (n >= N) return;
    const float* h = g_hA;   // final features land in A (A->B->A)
    float acc = __ldg(&hb[0]);
#pragma unroll 8
    for (int c = 0; c < HID; c++)
        acc = fmaf(h[n * HID + c], __ldg(&hw[c]), acc);
    int G = *ngp;
    int npg = N / G;
    int g = n / npg, r = n - g * npg;
    for (int d = 0; d < gfd; d++)
        acc = fmaf(__ldg(&gfeat[(g * gfd + d) * npg + r]), __ldg(&hw[HID + d]), acc);
    out[n] = acc;
}

// ---------------- launch ----------------
extern "C" void kernel_launch(void* const* d_in, const int* in_sizes, int n_in,
                              void* d_out, int out_size) {
    const float* x     = (const float*)d_in[0];
    const int*   eidx  = (const int*)d_in[1];
    const float* eattr = (const float*)d_in[2];
    const int*   ngp   = (const int*)d_in[3];
    const float* gfeat = (const float*)d_in[4];
    const float* src_w = (const float*)d_in[5];
    const float* src_b = (const float*)d_in[6];

    int N   = in_sizes[0] / INDIM;
    int E   = in_sizes[1] / 2;
    int gfd = in_sizes[4] / N;

    const int* src = eidx;
    const int* dst = eidx + E;

    const int MLP_SMEM = (4096 + 8192 + 8192 + 8192) * 4;   // 114688 B
    cudaFuncSetAttribute(k_mlp, cudaFuncAttributeMaxDynamicSharedMemorySize, MLP_SMEM);

    // CSR build + permuted/duplicated edge streams
    k_zero<<<(N + 255) / 256, 256>>>(N);
    k_hist<<<(E + 255) / 256, 256>>>(dst, E);
    int nb = (N + 1023) / 1024;
    k_scan1<<<nb, 1024>>>(N);
    k_scan2<<<1, 32>>>(nb);
    k_scan3<<<nb, 1024>>>(N, E);
    k_scatter<<<(E + 255) / 256, 256>>>(src, dst, (const float4*)eattr, E);

    // h0 = x @ src_w + src_b   (writes g_hA)
    k_inlin<<<(N * HID + 255) / 256, 256>>>(x, src_w, src_b, N);

    // layer 0: hA -> tmp -> hB
    k_agg<<<(N + 7) / 8, 256>>>(0, (const float*)d_in[7], (const float*)d_in[8], N);
    k_mlp<<<(N + 63) / 64, 256, MLP_SMEM>>>(0,
        (const float*)d_in[9],  (const float*)d_in[10],
        (const float*)d_in[11], (const float*)d_in[12],
        (const float*)d_in[13], (const float*)d_in[14], N);

    // layer 1: hB -> tmp -> hA
    k_agg<<<(N + 7) / 8, 256>>>(1, (const float*)d_in[15], (const float*)d_in[16], N);
    k_mlp<<<(N + 63) / 64, 256, MLP_SMEM>>>(1,
        (const float*)d_in[17], (const float*)d_in[18],
        (const float*)d_in[19], (const float*)d_in[20],
        (const float*)d_in[21], (const float*)d_in[22], N);

    // head
    k_head<<<(N + 255) / 256, 256>>>(gfeat, ngp,
        (const float*)d_in[23], (const float*)d_in[24],
        (float*)d_out, N, gfd);
    (void)n_in; (void)out_size;
}